// round 14
// baseline (speedup 1.0000x reference)
#include <cuda_runtime.h>
#include <cstdint>

// Embedding gather: out[i] = table[ids_flat[i]], D = 64 fp32 (256B/row).
// FINAL champion — best measured config from the full sweep (63.4us,
// DRAM 74%, traffic at the compulsory floor ~335MB):
// - 16 threads per row-chunk, one float4 per thread: line-granular gather
//   reads (256B row = exactly two 128B lines), fully coalesced stores.
// - 4 independent gathers per thread (quarters of the index space),
//   front-batched: 4 id LDGs -> 4 table LDG.128s in flight -> 4 streaming
//   stores. MLP sweep: {2:65.6, 4:63.4(best), 5:64.0, 8:65.5} us — the
//   L1tex wavefront-queue knee sits between 4 and 5.
// - __stcs output stores keep the table L2-resident so repeat ids (~31% of
//   rows) hit L2 instead of DRAM. Store-policy sweep: {.cs:63.4, .wt:64.2}.
// - Block sweep: {256:63.6, 512:63.4(best), 1024:63.7}. Persistent
//   grid-stride form regressed (68.4): one-shot grid wins.

__global__ void __launch_bounds__(512)
embed_gather_kernel(const int* __restrict__ ids,
                    const float4* __restrict__ table4,   // [VOCAB, 16] float4
                    float4* __restrict__ out4,           // [N, 16] float4
                    int n_rows, int vocab)
{
    long long total = (long long)n_rows * 16;            // total float4 chunks
    long long q     = total >> 2;                        // n_rows % 4 == 0 here
    long long g     = (long long)blockIdx.x * blockDim.x + threadIdx.x;

    if (g < q) {
        long long g0 = g, g1 = g + q, g2 = g + 2 * q, g3 = g + 3 * q;

        // Batch id loads (4 independent LDGs, broadcast within half-warp).
        int id0 = __ldg(&ids[(int)(g0 >> 4)]);
        int id1 = __ldg(&ids[(int)(g1 >> 4)]);
        int id2 = __ldg(&ids[(int)(g2 >> 4)]);
        int id3 = __ldg(&ids[(int)(g3 >> 4)]);
        if ((unsigned)id0 >= (unsigned)vocab) id0 = 0;
        if ((unsigned)id1 >= (unsigned)vocab) id1 = 0;
        if ((unsigned)id2 >= (unsigned)vocab) id2 = 0;
        if ((unsigned)id3 >= (unsigned)vocab) id3 = 0;

        int c0 = (int)(g0 & 15), c1 = (int)(g1 & 15);
        int c2 = (int)(g2 & 15), c3 = (int)(g3 & 15);

        // 4 independent gathers in flight.
        float4 v0 = __ldg(table4 + (long long)id0 * 16 + c0);
        float4 v1 = __ldg(table4 + (long long)id1 * 16 + c1);
        float4 v2 = __ldg(table4 + (long long)id2 * 16 + c2);
        float4 v3 = __ldg(table4 + (long long)id3 * 16 + c3);

        __stcs(out4 + g0, v0);      // streaming store: don't pollute L2
        __stcs(out4 + g1, v1);
        __stcs(out4 + g2, v2);
        __stcs(out4 + g3, v3);
    } else {
        // Tail for totals not divisible by 4 (not hit with these shapes).
        long long rem = 4 * q + (g - q);
        if (rem < total) {
            int row = (int)(rem >> 4), chunk = (int)(rem & 15);
            int id = __ldg(&ids[row]);
            if ((unsigned)id >= (unsigned)vocab) id = 0;
            __stcs(out4 + rem, __ldg(table4 + (long long)id * 16 + chunk));
        }
    }
}

extern "C" void kernel_launch(void* const* d_in, const int* in_sizes, int n_in,
                              void* d_out, int out_size)
{
    const int*    ids   = (const int*)d_in[0];
    const float4* table = (const float4*)d_in[1];
    float4*       out   = (float4*)d_out;

    int n_rows = in_sizes[0];                  // 819200
    int vocab  = in_sizes[1] / 64;             // 1,000,000

    long long total4   = (long long)n_rows * 16;     // 13,107,200
    long long q        = total4 >> 2;
    long long tail     = total4 - 4 * q;             // 0..3
    long long nthreads = q + tail;

    int threads = 512;
    int blocks  = (int)((nthreads + threads - 1) / threads);
    embed_gather_kernel<<<blocks, threads>>>(ids, table, out, n_rows, vocab);
}

// round 15
// speedup vs baseline: 1.0156x; 1.0156x over previous
#include <cuda_runtime.h>
#include <cstdint>

// Embedding gather: out[i] = table[ids_flat[i]], D = 64 fp32 (256B/row).
// FINAL champion — best measured config from the full sweep (63.4us,
// DRAM 74%, traffic at the compulsory floor ~335MB):
// - 16 threads per row-chunk, one float4 per thread: line-granular gather
//   reads (256B row = exactly two 128B lines), fully coalesced stores.
// - 4 independent gathers per thread (quarters of the index space),
//   front-batched: 4 id LDGs -> 4 table LDG.128s in flight -> 4 streaming
//   stores. MLP sweep: {2:65.6, 4:63.4(best), 5:64.0, 8:65.5} us — the
//   L1tex wavefront-queue knee sits between 4 and 5.
// - __stcs output stores keep the table L2-resident so repeat ids (~31% of
//   rows) hit L2 instead of DRAM. Store-policy sweep: {.cs:63.4, .wt:64.2}.
// - Block sweep: {256:63.6, 512:63.4(best), 1024:63.7}. Persistent
//   grid-stride form regressed (68.4): one-shot grid wins.
// - Run-to-run noise band for this config measured at ~±0.6us.

__global__ void __launch_bounds__(512)
embed_gather_kernel(const int* __restrict__ ids,
                    const float4* __restrict__ table4,   // [VOCAB, 16] float4
                    float4* __restrict__ out4,           // [N, 16] float4
                    int n_rows, int vocab)
{
    long long total = (long long)n_rows * 16;            // total float4 chunks
    long long q     = total >> 2;                        // n_rows % 4 == 0 here
    long long g     = (long long)blockIdx.x * blockDim.x + threadIdx.x;

    if (g < q) {
        long long g0 = g, g1 = g + q, g2 = g + 2 * q, g3 = g + 3 * q;

        // Batch id loads (4 independent LDGs, broadcast within half-warp).
        int id0 = __ldg(&ids[(int)(g0 >> 4)]);
        int id1 = __ldg(&ids[(int)(g1 >> 4)]);
        int id2 = __ldg(&ids[(int)(g2 >> 4)]);
        int id3 = __ldg(&ids[(int)(g3 >> 4)]);
        if ((unsigned)id0 >= (unsigned)vocab) id0 = 0;
        if ((unsigned)id1 >= (unsigned)vocab) id1 = 0;
        if ((unsigned)id2 >= (unsigned)vocab) id2 = 0;
        if ((unsigned)id3 >= (unsigned)vocab) id3 = 0;

        int c0 = (int)(g0 & 15), c1 = (int)(g1 & 15);
        int c2 = (int)(g2 & 15), c3 = (int)(g3 & 15);

        // 4 independent gathers in flight.
        float4 v0 = __ldg(table4 + (long long)id0 * 16 + c0);
        float4 v1 = __ldg(table4 + (long long)id1 * 16 + c1);
        float4 v2 = __ldg(table4 + (long long)id2 * 16 + c2);
        float4 v3 = __ldg(table4 + (long long)id3 * 16 + c3);

        __stcs(out4 + g0, v0);      // streaming store: don't pollute L2
        __stcs(out4 + g1, v1);
        __stcs(out4 + g2, v2);
        __stcs(out4 + g3, v3);
    } else {
        // Tail for totals not divisible by 4 (not hit with these shapes).
        long long rem = 4 * q + (g - q);
        if (rem < total) {
            int row = (int)(rem >> 4), chunk = (int)(rem & 15);
            int id = __ldg(&ids[row]);
            if ((unsigned)id >= (unsigned)vocab) id = 0;
            __stcs(out4 + rem, __ldg(table4 + (long long)id * 16 + chunk));
        }
    }
}

extern "C" void kernel_launch(void* const* d_in, const int* in_sizes, int n_in,
                              void* d_out, int out_size)
{
    const int*    ids   = (const int*)d_in[0];
    const float4* table = (const float4*)d_in[1];
    float4*       out   = (float4*)d_out;

    int n_rows = in_sizes[0];                  // 819200
    int vocab  = in_sizes[1] / 64;             // 1,000,000

    long long total4   = (long long)n_rows * 16;     // 13,107,200
    long long q        = total4 >> 2;
    long long tail     = total4 - 4 * q;             // 0..3
    long long nthreads = q + tail;

    int threads = 512;
    int blocks  = (int)((nthreads + threads - 1) / threads);
    embed_gather_kernel<<<blocks, threads>>>(ids, table, out, n_rows, vocab);
}

// round 16
// speedup vs baseline: 1.0171x; 1.0015x over previous
#include <cuda_runtime.h>
#include <cstdint>

// Embedding gather: out[i] = table[ids_flat[i]], D = 64 fp32 (256B/row).
// FINAL champion — best measured config from the full sweep (63.4us,
// DRAM 72-74%, traffic at the compulsory floor ~335MB):
// - 16 threads per row-chunk, one float4 per thread: line-granular gather
//   reads (256B row = exactly two 128B lines), fully coalesced stores.
// - 4 independent gathers per thread (quarters of the index space),
//   front-batched: 4 id LDGs -> 4 table LDG.128s in flight -> 4 streaming
//   stores. MLP sweep: {2:65.6, 4:63.4(best), 5:64.0, 8:65.5} us — the
//   L1tex wavefront-queue knee sits between 4 and 5.
// - __stcs output stores keep the table L2-resident so repeat ids (~31% of
//   rows) hit L2 instead of DRAM. Store-policy sweep: {.cs:63.4, .wt:64.2}.
// - Block sweep: {256:63.6, 512:63.4(best), 1024:63.7}. Persistent
//   grid-stride form regressed (68.4): one-shot grid wins.
// - Champion family measured 6x: {63.36..64.61}, median 63.5us (env noise).

__global__ void __launch_bounds__(512)
embed_gather_kernel(const int* __restrict__ ids,
                    const float4* __restrict__ table4,   // [VOCAB, 16] float4
                    float4* __restrict__ out4,           // [N, 16] float4
                    int n_rows, int vocab)
{
    long long total = (long long)n_rows * 16;            // total float4 chunks
    long long q     = total >> 2;                        // n_rows % 4 == 0 here
    long long g     = (long long)blockIdx.x * blockDim.x + threadIdx.x;

    if (g < q) {
        long long g0 = g, g1 = g + q, g2 = g + 2 * q, g3 = g + 3 * q;

        // Batch id loads (4 independent LDGs, broadcast within half-warp).
        int id0 = __ldg(&ids[(int)(g0 >> 4)]);
        int id1 = __ldg(&ids[(int)(g1 >> 4)]);
        int id2 = __ldg(&ids[(int)(g2 >> 4)]);
        int id3 = __ldg(&ids[(int)(g3 >> 4)]);
        if ((unsigned)id0 >= (unsigned)vocab) id0 = 0;
        if ((unsigned)id1 >= (unsigned)vocab) id1 = 0;
        if ((unsigned)id2 >= (unsigned)vocab) id2 = 0;
        if ((unsigned)id3 >= (unsigned)vocab) id3 = 0;

        int c0 = (int)(g0 & 15), c1 = (int)(g1 & 15);
        int c2 = (int)(g2 & 15), c3 = (int)(g3 & 15);

        // 4 independent gathers in flight.
        float4 v0 = __ldg(table4 + (long long)id0 * 16 + c0);
        float4 v1 = __ldg(table4 + (long long)id1 * 16 + c1);
        float4 v2 = __ldg(table4 + (long long)id2 * 16 + c2);
        float4 v3 = __ldg(table4 + (long long)id3 * 16 + c3);

        __stcs(out4 + g0, v0);      // streaming store: don't pollute L2
        __stcs(out4 + g1, v1);
        __stcs(out4 + g2, v2);
        __stcs(out4 + g3, v3);
    } else {
        // Tail for totals not divisible by 4 (not hit with these shapes).
        long long rem = 4 * q + (g - q);
        if (rem < total) {
            int row = (int)(rem >> 4), chunk = (int)(rem & 15);
            int id = __ldg(&ids[row]);
            if ((unsigned)id >= (unsigned)vocab) id = 0;
            __stcs(out4 + rem, __ldg(table4 + (long long)id * 16 + chunk));
        }
    }
}

extern "C" void kernel_launch(void* const* d_in, const int* in_sizes, int n_in,
                              void* d_out, int out_size)
{
    const int*    ids   = (const int*)d_in[0];
    const float4* table = (const float4*)d_in[1];
    float4*       out   = (float4*)d_out;

    int n_rows = in_sizes[0];                  // 819200
    int vocab  = in_sizes[1] / 64;             // 1,000,000

    long long total4   = (long long)n_rows * 16;     // 13,107,200
    long long q        = total4 >> 2;
    long long tail     = total4 - 4 * q;             // 0..3
    long long nthreads = q + tail;

    int threads = 512;
    int blocks  = (int)((nthreads + threads - 1) / threads);
    embed_gather_kernel<<<blocks, threads>>>(ids, table, out, n_rows, vocab);
}

// round 17
// speedup vs baseline: 1.0176x; 1.0005x over previous
#include <cuda_runtime.h>
#include <cstdint>

// Embedding gather: out[i] = table[ids_flat[i]], D = 64 fp32 (256B/row).
// Champion config (MLP=4, block=512, front-batched, __stcs stores) with
// __ldcg probe on the table gathers: skip L1 allocation (L1 reuse on a
// random 256MB table is ~nil; 228KB L1 can't help) -> less L1tex tag/data
// work per gather. Repeats still hit L2 (unchanged residency).
// - MLP sweep: {2:65.6, 4:63.4(best), 5:64.0, 8:65.5} us.
// - Block sweep: {256:63.6, 512:63.4(best), 1024:63.7} us.
// - Store sweep: {.cs:63.4(best), .wt:64.2} us.

__global__ void __launch_bounds__(512)
embed_gather_kernel(const int* __restrict__ ids,
                    const float4* __restrict__ table4,   // [VOCAB, 16] float4
                    float4* __restrict__ out4,           // [N, 16] float4
                    int n_rows, int vocab)
{
    long long total = (long long)n_rows * 16;            // total float4 chunks
    long long q     = total >> 2;                        // n_rows % 4 == 0 here
    long long g     = (long long)blockIdx.x * blockDim.x + threadIdx.x;

    if (g < q) {
        long long g0 = g, g1 = g + q, g2 = g + 2 * q, g3 = g + 3 * q;

        // Batch id loads (4 independent LDGs, broadcast within half-warp).
        // ids keep __ldg: same line read by 16 consecutive threads -> real
        // L1 broadcast reuse.
        int id0 = __ldg(&ids[(int)(g0 >> 4)]);
        int id1 = __ldg(&ids[(int)(g1 >> 4)]);
        int id2 = __ldg(&ids[(int)(g2 >> 4)]);
        int id3 = __ldg(&ids[(int)(g3 >> 4)]);
        if ((unsigned)id0 >= (unsigned)vocab) id0 = 0;
        if ((unsigned)id1 >= (unsigned)vocab) id1 = 0;
        if ((unsigned)id2 >= (unsigned)vocab) id2 = 0;
        if ((unsigned)id3 >= (unsigned)vocab) id3 = 0;

        int c0 = (int)(g0 & 15), c1 = (int)(g1 & 15);
        int c2 = (int)(g2 & 15), c3 = (int)(g3 & 15);

        // 4 independent gathers in flight; .cg = bypass L1 (no reuse there).
        float4 v0 = __ldcg(table4 + (long long)id0 * 16 + c0);
        float4 v1 = __ldcg(table4 + (long long)id1 * 16 + c1);
        float4 v2 = __ldcg(table4 + (long long)id2 * 16 + c2);
        float4 v3 = __ldcg(table4 + (long long)id3 * 16 + c3);

        __stcs(out4 + g0, v0);      // streaming store: don't pollute L2
        __stcs(out4 + g1, v1);
        __stcs(out4 + g2, v2);
        __stcs(out4 + g3, v3);
    } else {
        // Tail for totals not divisible by 4 (not hit with these shapes).
        long long rem = 4 * q + (g - q);
        if (rem < total) {
            int row = (int)(rem >> 4), chunk = (int)(rem & 15);
            int id = __ldg(&ids[row]);
            if ((unsigned)id >= (unsigned)vocab) id = 0;
            __stcs(out4 + rem, __ldcg(table4 + (long long)id * 16 + chunk));
        }
    }
}

extern "C" void kernel_launch(void* const* d_in, const int* in_sizes, int n_in,
                              void* d_out, int out_size)
{
    const int*    ids   = (const int*)d_in[0];
    const float4* table = (const float4*)d_in[1];
    float4*       out   = (float4*)d_out;

    int n_rows = in_sizes[0];                  // 819200
    int vocab  = in_sizes[1] / 64;             // 1,000,000

    long long total4   = (long long)n_rows * 16;     // 13,107,200
    long long q        = total4 >> 2;
    long long tail     = total4 - 4 * q;             // 0..3
    long long nthreads = q + tail;

    int threads = 512;
    int blocks  = (int)((nthreads + threads - 1) / threads);
    embed_gather_kernel<<<blocks, threads>>>(ids, table, out, n_rows, vocab);
}